// round 14
// baseline (speedup 1.0000x reference)
#include <cuda_runtime.h>
#include <math.h>

#define NNB  16
#define NOB  8
#define SDIM 4
#define H1   64
#define ED   16
#define HP   64
#define XC   85      // 1 + 4 + 64 + 16
#define BMAX 131072
#define NGRP 21      // 16 neighbor + 4 obstacle-pair + 1 goal group
#define TPB  128

// packed SoA scratch: g_xP[(grp*BMAX + b)*4 + c]
__device__ float g_xP[XC * BMAX];

// ---------------- all weights in ONE constant blob ----------------
struct __align__(16) CW {
    float Wp1n_t[H1 * 4];   // [h][4]  (transposed)
    float bp1n[H1];
    float Wp2n[H1 * ED];
    float bp2n[ED];         // pre-scaled by NNB
    float Wr1n[ED * H1];
    float br1n[H1];
    float Wr2n[H1 * ED];
    float br2n[ED];
    float Wp1o_t[H1 * 2];   // [h][2]  (transposed)
    float bp1o[H1];
    float Wp2o[H1 * ED];
    float bp2o[ED];         // pre-scaled by NOB
    float Wr1o[ED * H1];
    float br1o[H1];
    float Wr2o[H1 * ED];
    float br2o[ED];
    float Wpsi1[(2 * ED + SDIM) * HP];
    float bpsi1[HP];
    float Wpsi2[HP * 2];
    float bpsi2[2];
    float pad[2];
};

__constant__ CW cw;
__device__ CW g_wblob;

struct WPtrs { const float* p[20]; };

#define LDC4(arr, off) (*reinterpret_cast<const float4*>(&(arr)[off]))
#define LDC2(arr, off) (*reinterpret_cast<const float2*>(&(arr)[off]))

// ---------------- prep kernel: pack x AND gather weights in one launch ----------------
__global__ void __launch_bounds__(256)
prep_kernel(const float* __restrict__ x, int nb, int nbBlocks, WPtrs w)
{
    if (blockIdx.x >= (unsigned)nbBlocks) {
        const int a = blockIdx.x - nbBlocks;   // 0..17
        const int tid = threadIdx.x;
        if (a == 16) {                 // Wp1n transpose [4][64] -> [h][4]
            for (int i = tid; i < H1 * 4; i += 256) {
                int h = i >> 2, k = i & 3;
                g_wblob.Wp1n_t[i] = w.p[0][k * H1 + h];
            }
        } else if (a == 17) {          // Wp1o transpose + pre-scaled bp2n/bp2o
            for (int i = tid; i < H1 * 2; i += 256) {
                int h = i >> 1, k = i & 1;
                g_wblob.Wp1o_t[i] = w.p[8][k * H1 + h];
            }
            for (int i = tid; i < ED; i += 256) {
                g_wblob.bp2n[i] = (float)NNB * w.p[3][i];
                g_wblob.bp2o[i] = (float)NOB * w.p[11][i];
            }
        } else {
            float* dsts[16] = { g_wblob.bp1n, g_wblob.Wp2n, g_wblob.Wr1n, g_wblob.br1n,
                                g_wblob.Wr2n, g_wblob.br2n,
                                g_wblob.bp1o, g_wblob.Wp2o, g_wblob.Wr1o, g_wblob.br1o,
                                g_wblob.Wr2o, g_wblob.br2o,
                                g_wblob.Wpsi1, g_wblob.bpsi1, g_wblob.Wpsi2, g_wblob.bpsi2 };
            const int srci[16] = { 1, 2, 4, 5, 6, 7, 9, 10, 12, 13, 14, 15, 16, 17, 18, 19 };
            const int ns[16]   = { H1, H1*ED, ED*H1, H1, H1*ED, ED,
                                   H1, H1*ED, ED*H1, H1, H1*ED, ED,
                                   (2*ED+SDIM)*HP, HP, HP*2, 2 };
            float* dst = dsts[a];
            const float* src = w.p[srci[a]];
            const int n = ns[a];
            for (int i = tid; i < n; i += 256)
                dst[i] = src[i];
        }
        return;
    }

    // ---- x packing ----
    __shared__ __align__(16) float buf[32 * 85];
    const int bBase = blockIdx.x * 32;

    if (bBase + 32 <= nb) {
        const float4* src = reinterpret_cast<const float4*>(x + (size_t)bBase * 85);
        float4* dst = reinterpret_cast<float4*>(buf);
        #pragma unroll 4
        for (int i = threadIdx.x; i < 680; i += 256)
            dst[i] = src[i];
    } else {
        for (int i = threadIdx.x; i < 32 * 85; i += 256) {
            const int r = i / 85, f = i - 85 * r;
            const int b = bBase + r;
            buf[i] = (b < nb) ? x[(size_t)b * 85 + f] : 0.f;
        }
    }
    __syncthreads();

    const int bl = threadIdx.x & 31;
    const int b  = bBase + bl;
    if (b < nb) {
        const float* row = buf + bl * 85;
        for (int g = threadIdx.x >> 5; g < NGRP; g += 8) {
            const int fb = (g < 16) ? (5 + 4 * g) : (g < 20 ? (69 + 4 * (g - 16)) : 1);
            float4 v;
            v.x = row[fb];     v.y = row[fb + 1];
            v.z = row[fb + 2]; v.w = row[fb + 3];
            *reinterpret_cast<float4*>(&g_xP[((size_t)g * BMAX + b) * 4]) = v;
        }
    }
}

__device__ __forceinline__ void barrier_acc(float e0, float e1, float D,
                                            float& bx, float& by) {
    const float px = -e0, py = -e1;
    const float q  = fmaf(px, px, py * py);
    const float rq = rsqrtf(q);
    const float nrm = q * rq;
    const float s  = 0.05f * __fdividef(1.0f, nrm * (nrm - D));
    bx = fmaf(s, px, bx);
    by = fmaf(s, py, by);
}

__global__ void __launch_bounds__(TPB, 5)
bnet_kernel(float* __restrict__ out, int nb)
{
    const int t = blockIdx.x * TPB + threadIdx.x;
    if (t >= nb) return;

    const float4* xp = reinterpret_cast<const float4*>(g_xP);

    float bx = 0.f, by = 0.f;
    float rn[ED], ro[ED], sp[ED];

    // ======================= neighbor deep-set =======================
    // 16 neighbors in 4 groups of 4 (small live set for 102-reg cap).
    {
        float hs[H1];
        #pragma unroll
        for (int h = 0; h < H1; ++h) hs[h] = 0.f;

        #pragma unroll 1
        for (int g = 0; g < 4; ++g) {
            float e[16];
            #pragma unroll
            for (int j = 0; j < 4; ++j) {
                const float4 v = xp[(size_t)(4 * g + j) * BMAX + t];
                e[4 * j + 0] = v.x; e[4 * j + 1] = v.y;
                e[4 * j + 2] = v.z; e[4 * j + 3] = v.w;
            }
            #pragma unroll
            for (int k = 0; k < 4; ++k)
                barrier_acc(e[4 * k + 0], e[4 * k + 1], 0.3f, bx, by);

            #pragma unroll
            for (int h = 0; h < H1; ++h) {
                const float4 w = LDC4(cw.Wp1n_t, h * 4);
                const float b  = cw.bp1n[h];
                float v0 = b, v1 = b, v2 = b, v3 = b;
                v0 = fmaf(e[0],  w.x, v0); v0 = fmaf(e[1],  w.y, v0);
                v0 = fmaf(e[2],  w.z, v0); v0 = fmaf(e[3],  w.w, v0);
                v1 = fmaf(e[4],  w.x, v1); v1 = fmaf(e[5],  w.y, v1);
                v1 = fmaf(e[6],  w.z, v1); v1 = fmaf(e[7],  w.w, v1);
                v2 = fmaf(e[8],  w.x, v2); v2 = fmaf(e[9],  w.y, v2);
                v2 = fmaf(e[10], w.z, v2); v2 = fmaf(e[11], w.w, v2);
                v3 = fmaf(e[12], w.x, v3); v3 = fmaf(e[13], w.y, v3);
                v3 = fmaf(e[14], w.z, v3); v3 = fmaf(e[15], w.w, v3);
                hs[h] += (fmaxf(v0, 0.f) + fmaxf(v1, 0.f))
                       + (fmaxf(v2, 0.f) + fmaxf(v3, 0.f));
            }
        }

        #pragma unroll
        for (int j = 0; j < 4; ++j) {
            const float4 b = LDC4(cw.bp2n, 4 * j);
            sp[4*j+0] = b.x; sp[4*j+1] = b.y; sp[4*j+2] = b.z; sp[4*j+3] = b.w;
        }
        #pragma unroll
        for (int h = 0; h < H1; ++h) {
            const float v = hs[h];
            #pragma unroll
            for (int j = 0; j < 4; ++j) {
                const float4 w = LDC4(cw.Wp2n, h * ED + 4 * j);
                sp[4*j+0] = fmaf(v, w.x, sp[4*j+0]);
                sp[4*j+1] = fmaf(v, w.y, sp[4*j+1]);
                sp[4*j+2] = fmaf(v, w.z, sp[4*j+2]);
                sp[4*j+3] = fmaf(v, w.w, sp[4*j+3]);
            }
        }
    }
    // rho_n
    #pragma unroll
    for (int j = 0; j < 4; ++j) {
        const float4 b = LDC4(cw.br2n, 4 * j);
        rn[4*j+0] = b.x; rn[4*j+1] = b.y; rn[4*j+2] = b.z; rn[4*j+3] = b.w;
    }
    #pragma unroll 1
    for (int c = 0; c < 4; ++c) {
        const int base = c * 16;
        float hc[16];
        #pragma unroll
        for (int q = 0; q < 4; ++q) {
            const float4 b = LDC4(cw.br1n, base + 4 * q);
            hc[4*q+0] = b.x; hc[4*q+1] = b.y; hc[4*q+2] = b.z; hc[4*q+3] = b.w;
        }
        #pragma unroll
        for (int i = 0; i < ED; ++i) {
            const float v = sp[i];
            #pragma unroll
            for (int j = 0; j < 4; ++j) {
                const float4 w = LDC4(cw.Wr1n, i * H1 + base + 4 * j);
                hc[4*j+0] = fmaf(v, w.x, hc[4*j+0]);
                hc[4*j+1] = fmaf(v, w.y, hc[4*j+1]);
                hc[4*j+2] = fmaf(v, w.z, hc[4*j+2]);
                hc[4*j+3] = fmaf(v, w.w, hc[4*j+3]);
            }
        }
        #pragma unroll
        for (int h = 0; h < 16; ++h) {
            const float v = fmaxf(hc[h], 0.f);
            #pragma unroll
            for (int j = 0; j < 4; ++j) {
                const float4 w = LDC4(cw.Wr2n, (base + h) * ED + 4 * j);
                rn[4*j+0] = fmaf(v, w.x, rn[4*j+0]);
                rn[4*j+1] = fmaf(v, w.y, rn[4*j+1]);
                rn[4*j+2] = fmaf(v, w.z, rn[4*j+2]);
                rn[4*j+3] = fmaf(v, w.w, rn[4*j+3]);
            }
        }
    }

    // ======================= obstacle deep-set =======================
    {
        float e[16];
        #pragma unroll
        for (int j = 0; j < 4; ++j) {
            const float4 v = xp[(size_t)(16 + j) * BMAX + t];
            e[4 * j + 0] = v.x; e[4 * j + 1] = v.y;
            e[4 * j + 2] = v.z; e[4 * j + 3] = v.w;
        }
        #pragma unroll
        for (int k = 0; k < 8; ++k)
            barrier_acc(e[2 * k + 0], e[2 * k + 1], 0.3f, bx, by);

        float hs[H1];
        #pragma unroll
        for (int h = 0; h < H1; ++h) {
            const float2 w = LDC2(cw.Wp1o_t, h * 2);
            const float b  = cw.bp1o[h];
            float acc0 = 0.f, acc1 = 0.f;
            #pragma unroll
            for (int k = 0; k < 8; k += 2) {
                float va = b, vb = b;
                va = fmaf(e[2 * k + 0], w.x, va);
                va = fmaf(e[2 * k + 1], w.y, va);
                vb = fmaf(e[2 * k + 2], w.x, vb);
                vb = fmaf(e[2 * k + 3], w.y, vb);
                acc0 += fmaxf(va, 0.f);
                acc1 += fmaxf(vb, 0.f);
            }
            hs[h] = acc0 + acc1;
        }

        #pragma unroll
        for (int j = 0; j < 4; ++j) {
            const float4 b = LDC4(cw.bp2o, 4 * j);
            sp[4*j+0] = b.x; sp[4*j+1] = b.y; sp[4*j+2] = b.z; sp[4*j+3] = b.w;
        }
        #pragma unroll
        for (int h = 0; h < H1; ++h) {
            const float v = hs[h];
            #pragma unroll
            for (int j = 0; j < 4; ++j) {
                const float4 w = LDC4(cw.Wp2o, h * ED + 4 * j);
                sp[4*j+0] = fmaf(v, w.x, sp[4*j+0]);
                sp[4*j+1] = fmaf(v, w.y, sp[4*j+1]);
                sp[4*j+2] = fmaf(v, w.z, sp[4*j+2]);
                sp[4*j+3] = fmaf(v, w.w, sp[4*j+3]);
            }
        }
    }
    #pragma unroll
    for (int j = 0; j < 4; ++j) {
        const float4 b = LDC4(cw.br2o, 4 * j);
        ro[4*j+0] = b.x; ro[4*j+1] = b.y; ro[4*j+2] = b.z; ro[4*j+3] = b.w;
    }
    #pragma unroll 1
    for (int c = 0; c < 4; ++c) {
        const int base = c * 16;
        float hc[16];
        #pragma unroll
        for (int q = 0; q < 4; ++q) {
            const float4 b = LDC4(cw.br1o, base + 4 * q);
            hc[4*q+0] = b.x; hc[4*q+1] = b.y; hc[4*q+2] = b.z; hc[4*q+3] = b.w;
        }
        #pragma unroll
        for (int i = 0; i < ED; ++i) {
            const float v = sp[i];
            #pragma unroll
            for (int j = 0; j < 4; ++j) {
                const float4 w = LDC4(cw.Wr1o, i * H1 + base + 4 * j);
                hc[4*j+0] = fmaf(v, w.x, hc[4*j+0]);
                hc[4*j+1] = fmaf(v, w.y, hc[4*j+1]);
                hc[4*j+2] = fmaf(v, w.z, hc[4*j+2]);
                hc[4*j+3] = fmaf(v, w.w, hc[4*j+3]);
            }
        }
        #pragma unroll
        for (int h = 0; h < 16; ++h) {
            const float v = fmaxf(hc[h], 0.f);
            #pragma unroll
            for (int j = 0; j < 4; ++j) {
                const float4 w = LDC4(cw.Wr2o, (base + h) * ED + 4 * j);
                ro[4*j+0] = fmaf(v, w.x, ro[4*j+0]);
                ro[4*j+1] = fmaf(v, w.y, ro[4*j+1]);
                ro[4*j+2] = fmaf(v, w.z, ro[4*j+2]);
                ro[4*j+3] = fmaf(v, w.w, ro[4*j+3]);
            }
        }
    }

    // ======================= psi head =======================
    const float4 gv = xp[(size_t)20 * BMAX + t];
    const float gs[4] = { gv.x, gv.y, gv.z, gv.w };
    float a0 = cw.bpsi2[0], a1 = cw.bpsi2[1];
    #pragma unroll 1
    for (int c = 0; c < 4; ++c) {
        const int base = c * 16;
        float hc[16];
        #pragma unroll
        for (int q = 0; q < 4; ++q) {
            const float4 b = LDC4(cw.bpsi1, base + 4 * q);
            hc[4*q+0] = b.x; hc[4*q+1] = b.y; hc[4*q+2] = b.z; hc[4*q+3] = b.w;
        }
        #pragma unroll
        for (int i = 0; i < ED; ++i) {
            const float v = rn[i];
            #pragma unroll
            for (int j = 0; j < 4; ++j) {
                const float4 w = LDC4(cw.Wpsi1, i * HP + base + 4 * j);
                hc[4*j+0] = fmaf(v, w.x, hc[4*j+0]);
                hc[4*j+1] = fmaf(v, w.y, hc[4*j+1]);
                hc[4*j+2] = fmaf(v, w.z, hc[4*j+2]);
                hc[4*j+3] = fmaf(v, w.w, hc[4*j+3]);
            }
        }
        #pragma unroll
        for (int i = 0; i < ED; ++i) {
            const float v = ro[i];
            #pragma unroll
            for (int j = 0; j < 4; ++j) {
                const float4 w = LDC4(cw.Wpsi1, (ED + i) * HP + base + 4 * j);
                hc[4*j+0] = fmaf(v, w.x, hc[4*j+0]);
                hc[4*j+1] = fmaf(v, w.y, hc[4*j+1]);
                hc[4*j+2] = fmaf(v, w.z, hc[4*j+2]);
                hc[4*j+3] = fmaf(v, w.w, hc[4*j+3]);
            }
        }
        #pragma unroll
        for (int k = 0; k < 4; ++k) {
            const float v = gs[k];
            #pragma unroll
            for (int j = 0; j < 4; ++j) {
                const float4 w = LDC4(cw.Wpsi1, (2 * ED + k) * HP + base + 4 * j);
                hc[4*j+0] = fmaf(v, w.x, hc[4*j+0]);
                hc[4*j+1] = fmaf(v, w.y, hc[4*j+1]);
                hc[4*j+2] = fmaf(v, w.z, hc[4*j+2]);
                hc[4*j+3] = fmaf(v, w.w, hc[4*j+3]);
            }
        }
        #pragma unroll
        for (int h = 0; h < 16; h += 2) {
            const float v0 = fmaxf(hc[h], 0.f);
            const float v1 = fmaxf(hc[h + 1], 0.f);
            const float4 w = LDC4(cw.Wpsi2, 2 * (base + h));
            a0 = fmaf(v0, w.x, a0); a1 = fmaf(v0, w.y, a1);
            a0 = fmaf(v1, w.z, a0); a1 = fmaf(v1, w.w, a1);
        }
    }

    a0 = fmaf(2.0f, tanhf(a0), bx);
    a1 = fmaf(2.0f, tanhf(a1), by);

    const float inv = fmaxf(fmaxf(fabsf(a0), fabsf(a1)) * 0.5f, 1.0f);
    const float r   = __fdividef(1.0f, inv);
    float2 res;
    res.x = a0 * r;
    res.y = a1 * r;
    reinterpret_cast<float2*>(out)[t] = res;
}

extern "C" void kernel_launch(void* const* d_in, const int* in_sizes, int n_in,
                              void* d_out, int out_size) {
    const float* x = (const float*)d_in[0];
    float* out = (float*)d_out;
    const int nb = in_sizes[0] / XC;

    WPtrs w;
    for (int i = 0; i < 20; ++i) w.p[i] = (const float*)d_in[i + 1];

    const int nbBlocks = (nb + 31) / 32;
    prep_kernel<<<nbBlocks + 18, 256>>>(x, nb, nbBlocks, w);

    void* blobAddr = nullptr;
    cudaGetSymbolAddress(&blobAddr, g_wblob);
    cudaMemcpyToSymbolAsync(cw, blobAddr, sizeof(CW), 0, cudaMemcpyDeviceToDevice, 0);

    const int blocks = (nb + TPB - 1) / TPB;
    bnet_kernel<<<blocks, TPB>>>(out, nb);
}

// round 15
// speedup vs baseline: 1.0928x; 1.0928x over previous
#include <cuda_runtime.h>
#include <math.h>

#define NNB  16
#define NOB  8
#define SDIM 4
#define H1   64
#define ED   16
#define HP   64
#define XC   85
#define BMAX 131072
#define NGRP 21
#define TPB  256

__device__ float g_xP[XC * BMAX];

struct __align__(16) CW {
    float Wp1n_t[H1 * 4];
    float bp1n[H1];
    float Wp2n[H1 * ED];
    float bp2n[ED];         // pre-scaled by NNB
    float Wr1n[ED * H1];
    float br1n[H1];
    float Wr2n[H1 * ED];
    float br2n[ED];
    float Wp1o_t[H1 * 2];
    float bp1o[H1];
    float Wp2o[H1 * ED];
    float bp2o[ED];         // pre-scaled by NOB
    float Wr1o[ED * H1];
    float br1o[H1];
    float Wr2o[H1 * ED];
    float br2o[ED];
    float Wpsi1[(2 * ED + SDIM) * HP];
    float bpsi1[HP];
    float Wpsi2[HP * 2];
    float bpsi2[2];
    float pad[2];
};

__constant__ CW cw;
__device__ CW g_wblob;

struct WPtrs { const float* p[20]; };

#define LDC4(arr, off) (*reinterpret_cast<const float4*>(&(arr)[off]))
#define LDC2(arr, off) (*reinterpret_cast<const float2*>(&(arr)[off]))

// ---------------- prep kernel (unchanged from R13) ----------------
__global__ void __launch_bounds__(256)
prep_kernel(const float* __restrict__ x, int nb, int nbBlocks, WPtrs w)
{
    if (blockIdx.x >= (unsigned)nbBlocks) {
        const int a = blockIdx.x - nbBlocks;
        const int tid = threadIdx.x;
        if (a == 16) {
            for (int i = tid; i < H1 * 4; i += 256) {
                int h = i >> 2, k = i & 3;
                g_wblob.Wp1n_t[i] = w.p[0][k * H1 + h];
            }
        } else if (a == 17) {
            for (int i = tid; i < H1 * 2; i += 256) {
                int h = i >> 1, k = i & 1;
                g_wblob.Wp1o_t[i] = w.p[8][k * H1 + h];
            }
            for (int i = tid; i < ED; i += 256) {
                g_wblob.bp2n[i] = (float)NNB * w.p[3][i];
                g_wblob.bp2o[i] = (float)NOB * w.p[11][i];
            }
        } else {
            float* dsts[16] = { g_wblob.bp1n, g_wblob.Wp2n, g_wblob.Wr1n, g_wblob.br1n,
                                g_wblob.Wr2n, g_wblob.br2n,
                                g_wblob.bp1o, g_wblob.Wp2o, g_wblob.Wr1o, g_wblob.br1o,
                                g_wblob.Wr2o, g_wblob.br2o,
                                g_wblob.Wpsi1, g_wblob.bpsi1, g_wblob.Wpsi2, g_wblob.bpsi2 };
            const int srci[16] = { 1, 2, 4, 5, 6, 7, 9, 10, 12, 13, 14, 15, 16, 17, 18, 19 };
            const int ns[16]   = { H1, H1*ED, ED*H1, H1, H1*ED, ED,
                                   H1, H1*ED, ED*H1, H1, H1*ED, ED,
                                   (2*ED+SDIM)*HP, HP, HP*2, 2 };
            float* dst = dsts[a];
            const float* src = w.p[srci[a]];
            const int n = ns[a];
            for (int i = tid; i < n; i += 256)
                dst[i] = src[i];
        }
        return;
    }

    __shared__ __align__(16) float buf[32 * 85];
    const int bBase = blockIdx.x * 32;

    if (bBase + 32 <= nb) {
        const float4* src = reinterpret_cast<const float4*>(x + (size_t)bBase * 85);
        float4* dst = reinterpret_cast<float4*>(buf);
        #pragma unroll 4
        for (int i = threadIdx.x; i < 680; i += 256)
            dst[i] = src[i];
    } else {
        for (int i = threadIdx.x; i < 32 * 85; i += 256) {
            const int r = i / 85, f = i - 85 * r;
            const int b = bBase + r;
            buf[i] = (b < nb) ? x[(size_t)b * 85 + f] : 0.f;
        }
    }
    __syncthreads();

    const int bl = threadIdx.x & 31;
    const int b  = bBase + bl;
    if (b < nb) {
        const float* row = buf + bl * 85;
        for (int g = threadIdx.x >> 5; g < NGRP; g += 8) {
            const int fb = (g < 16) ? (5 + 4 * g) : (g < 20 ? (69 + 4 * (g - 16)) : 1);
            float4 v;
            v.x = row[fb];     v.y = row[fb + 1];
            v.z = row[fb + 2]; v.w = row[fb + 3];
            *reinterpret_cast<float4*>(&g_xP[((size_t)g * BMAX + b) * 4]) = v;
        }
    }
}

__device__ __forceinline__ void barrier_acc(float e0, float e1, float D,
                                            float& bx, float& by) {
    const float px = -e0, py = -e1;
    const float q  = fmaf(px, px, py * py);
    const float rq = rsqrtf(q);
    const float nrm = q * rq;
    const float s  = 0.05f * __fdividef(1.0f, nrm * (nrm - D));
    bx = fmaf(s, px, bx);
    by = fmaf(s, py, by);
}

// φn for one element: hs[64] over 2 groups of 8, then Wp2n GEMV -> sp[16]
__device__ __forceinline__ void phi_n_f(const float4* __restrict__ xp, int t,
                                        float sp[ED], float& bx, float& by)
{
    float hs[H1];
    #pragma unroll
    for (int h = 0; h < H1; ++h) hs[h] = 0.f;

    #pragma unroll 1
    for (int g = 0; g < 2; ++g) {
        float e[32];
        #pragma unroll
        for (int j = 0; j < 8; ++j) {
            const float4 v = xp[(size_t)(8 * g + j) * BMAX + t];
            e[4*j+0] = v.x; e[4*j+1] = v.y; e[4*j+2] = v.z; e[4*j+3] = v.w;
        }
        #pragma unroll
        for (int k = 0; k < 8; ++k)
            barrier_acc(e[4*k+0], e[4*k+1], 0.3f, bx, by);

        #pragma unroll
        for (int h = 0; h < H1; ++h) {
            const float4 w = LDC4(cw.Wp1n_t, h * 4);
            const float b  = cw.bp1n[h];
            float v0 = b, v1 = b, v2 = b, v3 = b;
            float v4 = b, v5 = b, v6 = b, v7 = b;
            v0 = fmaf(e[0],  w.x, v0); v0 = fmaf(e[1],  w.y, v0);
            v0 = fmaf(e[2],  w.z, v0); v0 = fmaf(e[3],  w.w, v0);
            v1 = fmaf(e[4],  w.x, v1); v1 = fmaf(e[5],  w.y, v1);
            v1 = fmaf(e[6],  w.z, v1); v1 = fmaf(e[7],  w.w, v1);
            v2 = fmaf(e[8],  w.x, v2); v2 = fmaf(e[9],  w.y, v2);
            v2 = fmaf(e[10], w.z, v2); v2 = fmaf(e[11], w.w, v2);
            v3 = fmaf(e[12], w.x, v3); v3 = fmaf(e[13], w.y, v3);
            v3 = fmaf(e[14], w.z, v3); v3 = fmaf(e[15], w.w, v3);
            v4 = fmaf(e[16], w.x, v4); v4 = fmaf(e[17], w.y, v4);
            v4 = fmaf(e[18], w.z, v4); v4 = fmaf(e[19], w.w, v4);
            v5 = fmaf(e[20], w.x, v5); v5 = fmaf(e[21], w.y, v5);
            v5 = fmaf(e[22], w.z, v5); v5 = fmaf(e[23], w.w, v5);
            v6 = fmaf(e[24], w.x, v6); v6 = fmaf(e[25], w.y, v6);
            v6 = fmaf(e[26], w.z, v6); v6 = fmaf(e[27], w.w, v6);
            v7 = fmaf(e[28], w.x, v7); v7 = fmaf(e[29], w.y, v7);
            v7 = fmaf(e[30], w.z, v7); v7 = fmaf(e[31], w.w, v7);
            const float s0 = (fmaxf(v0, 0.f) + fmaxf(v1, 0.f))
                           + (fmaxf(v2, 0.f) + fmaxf(v3, 0.f));
            const float s1 = (fmaxf(v4, 0.f) + fmaxf(v5, 0.f))
                           + (fmaxf(v6, 0.f) + fmaxf(v7, 0.f));
            hs[h] += s0 + s1;
        }
    }

    #pragma unroll
    for (int j = 0; j < 4; ++j) {
        const float4 b = LDC4(cw.bp2n, 4 * j);
        sp[4*j+0] = b.x; sp[4*j+1] = b.y; sp[4*j+2] = b.z; sp[4*j+3] = b.w;
    }
    #pragma unroll
    for (int h = 0; h < H1; ++h) {
        const float v = hs[h];
        #pragma unroll
        for (int j = 0; j < 4; ++j) {
            const float4 w = LDC4(cw.Wp2n, h * ED + 4 * j);
            sp[4*j+0] = fmaf(v, w.x, sp[4*j+0]);
            sp[4*j+1] = fmaf(v, w.y, sp[4*j+1]);
            sp[4*j+2] = fmaf(v, w.z, sp[4*j+2]);
            sp[4*j+3] = fmaf(v, w.w, sp[4*j+3]);
        }
    }
}

// φo fused for one element: per-h value folded straight into sp GEMV (no hs array)
__device__ __forceinline__ void phi_o_f(const float4* __restrict__ xp, int t,
                                        float sp[ED], float& bx, float& by)
{
    float e[16];
    #pragma unroll
    for (int j = 0; j < 4; ++j) {
        const float4 v = xp[(size_t)(16 + j) * BMAX + t];
        e[4*j+0] = v.x; e[4*j+1] = v.y; e[4*j+2] = v.z; e[4*j+3] = v.w;
    }
    #pragma unroll
    for (int k = 0; k < 8; ++k)
        barrier_acc(e[2*k+0], e[2*k+1], 0.3f, bx, by);

    #pragma unroll
    for (int j = 0; j < 4; ++j) {
        const float4 b = LDC4(cw.bp2o, 4 * j);
        sp[4*j+0] = b.x; sp[4*j+1] = b.y; sp[4*j+2] = b.z; sp[4*j+3] = b.w;
    }
    #pragma unroll
    for (int h = 0; h < H1; ++h) {
        const float2 w = LDC2(cw.Wp1o_t, h * 2);
        const float b  = cw.bp1o[h];
        float acc0 = 0.f, acc1 = 0.f;
        #pragma unroll
        for (int k = 0; k < 8; k += 2) {
            float va = b, vb = b;
            va = fmaf(e[2*k+0], w.x, va);
            va = fmaf(e[2*k+1], w.y, va);
            vb = fmaf(e[2*k+2], w.x, vb);
            vb = fmaf(e[2*k+3], w.y, vb);
            acc0 += fmaxf(va, 0.f);
            acc1 += fmaxf(vb, 0.f);
        }
        const float v = acc0 + acc1;
        #pragma unroll
        for (int j = 0; j < 4; ++j) {
            const float4 w4 = LDC4(cw.Wp2o, h * ED + 4 * j);
            sp[4*j+0] = fmaf(v, w4.x, sp[4*j+0]);
            sp[4*j+1] = fmaf(v, w4.y, sp[4*j+1]);
            sp[4*j+2] = fmaf(v, w4.z, sp[4*j+2]);
            sp[4*j+3] = fmaf(v, w4.w, sp[4*j+3]);
        }
    }
}

// ======================= main kernel: 2 elements per thread =======================
__global__ void __launch_bounds__(TPB, 2)
bnet_kernel(float* __restrict__ out, int nb)
{
    __shared__ float sA[TPB * 17];
    __shared__ float sB[TPB * 17];

    const int tid = threadIdx.x;
    const int t0  = blockIdx.x * (2 * TPB) + tid;
    if (t0 >= nb) return;
    int t1 = t0 + TPB;
    const bool hasB = (t1 < nb);
    if (!hasB) t1 = t0;

    const float4* xp = reinterpret_cast<const float4*>(g_xP);
    float* mySA = &sA[tid * 17];
    float* mySB = &sB[tid * 17];

    float bxA = 0.f, byA = 0.f, bxB = 0.f, byB = 0.f;
    float spA[ED], spB[ED];

    // ---- phi_n for both elements (spA parked in smem during B's pass) ----
    phi_n_f(xp, t0, spA, bxA, byA);
    #pragma unroll
    for (int i = 0; i < ED; ++i) mySA[i] = spA[i];
    phi_n_f(xp, t1, spB, bxB, byB);
    #pragma unroll
    for (int i = 0; i < ED; ++i) spA[i] = mySA[i];

    // ---- dual rho_n: shared weight loads feed both elements ----
    float rnA[ED], rnB[ED];
    #pragma unroll
    for (int j = 0; j < 4; ++j) {
        const float4 b = LDC4(cw.br2n, 4 * j);
        rnA[4*j+0] = b.x; rnA[4*j+1] = b.y; rnA[4*j+2] = b.z; rnA[4*j+3] = b.w;
        rnB[4*j+0] = b.x; rnB[4*j+1] = b.y; rnB[4*j+2] = b.z; rnB[4*j+3] = b.w;
    }
    #pragma unroll 1
    for (int c = 0; c < 4; ++c) {
        const int base = c * 16;
        float hA[16], hB[16];
        #pragma unroll
        for (int q = 0; q < 4; ++q) {
            const float4 b = LDC4(cw.br1n, base + 4 * q);
            hA[4*q+0] = b.x; hA[4*q+1] = b.y; hA[4*q+2] = b.z; hA[4*q+3] = b.w;
            hB[4*q+0] = b.x; hB[4*q+1] = b.y; hB[4*q+2] = b.z; hB[4*q+3] = b.w;
        }
        #pragma unroll
        for (int i = 0; i < ED; ++i) {
            const float vA = spA[i], vB = spB[i];
            #pragma unroll
            for (int j = 0; j < 4; ++j) {
                const float4 w = LDC4(cw.Wr1n, i * H1 + base + 4 * j);
                hA[4*j+0] = fmaf(vA, w.x, hA[4*j+0]);
                hA[4*j+1] = fmaf(vA, w.y, hA[4*j+1]);
                hA[4*j+2] = fmaf(vA, w.z, hA[4*j+2]);
                hA[4*j+3] = fmaf(vA, w.w, hA[4*j+3]);
                hB[4*j+0] = fmaf(vB, w.x, hB[4*j+0]);
                hB[4*j+1] = fmaf(vB, w.y, hB[4*j+1]);
                hB[4*j+2] = fmaf(vB, w.z, hB[4*j+2]);
                hB[4*j+3] = fmaf(vB, w.w, hB[4*j+3]);
            }
        }
        #pragma unroll
        for (int h = 0; h < 16; ++h) {
            const float vA = fmaxf(hA[h], 0.f);
            const float vB = fmaxf(hB[h], 0.f);
            #pragma unroll
            for (int j = 0; j < 4; ++j) {
                const float4 w = LDC4(cw.Wr2n, (base + h) * ED + 4 * j);
                rnA[4*j+0] = fmaf(vA, w.x, rnA[4*j+0]);
                rnA[4*j+1] = fmaf(vA, w.y, rnA[4*j+1]);
                rnA[4*j+2] = fmaf(vA, w.z, rnA[4*j+2]);
                rnA[4*j+3] = fmaf(vA, w.w, rnA[4*j+3]);
                rnB[4*j+0] = fmaf(vB, w.x, rnB[4*j+0]);
                rnB[4*j+1] = fmaf(vB, w.y, rnB[4*j+1]);
                rnB[4*j+2] = fmaf(vB, w.z, rnB[4*j+2]);
                rnB[4*j+3] = fmaf(vB, w.w, rnB[4*j+3]);
            }
        }
    }
    // park rn in smem across the phi_o passes
    #pragma unroll
    for (int i = 0; i < ED; ++i) { mySA[i] = rnA[i]; mySB[i] = rnB[i]; }

    // ---- phi_o for both elements (fused, low pressure) ----
    phi_o_f(xp, t0, spA, bxA, byA);
    phi_o_f(xp, t1, spB, bxB, byB);

    // ---- dual rho_o ----
    float roA[ED], roB[ED];
    #pragma unroll
    for (int j = 0; j < 4; ++j) {
        const float4 b = LDC4(cw.br2o, 4 * j);
        roA[4*j+0] = b.x; roA[4*j+1] = b.y; roA[4*j+2] = b.z; roA[4*j+3] = b.w;
        roB[4*j+0] = b.x; roB[4*j+1] = b.y; roB[4*j+2] = b.z; roB[4*j+3] = b.w;
    }
    #pragma unroll 1
    for (int c = 0; c < 4; ++c) {
        const int base = c * 16;
        float hA[16], hB[16];
        #pragma unroll
        for (int q = 0; q < 4; ++q) {
            const float4 b = LDC4(cw.br1o, base + 4 * q);
            hA[4*q+0] = b.x; hA[4*q+1] = b.y; hA[4*q+2] = b.z; hA[4*q+3] = b.w;
            hB[4*q+0] = b.x; hB[4*q+1] = b.y; hB[4*q+2] = b.z; hB[4*q+3] = b.w;
        }
        #pragma unroll
        for (int i = 0; i < ED; ++i) {
            const float vA = spA[i], vB = spB[i];
            #pragma unroll
            for (int j = 0; j < 4; ++j) {
                const float4 w = LDC4(cw.Wr1o, i * H1 + base + 4 * j);
                hA[4*j+0] = fmaf(vA, w.x, hA[4*j+0]);
                hA[4*j+1] = fmaf(vA, w.y, hA[4*j+1]);
                hA[4*j+2] = fmaf(vA, w.z, hA[4*j+2]);
                hA[4*j+3] = fmaf(vA, w.w, hA[4*j+3]);
                hB[4*j+0] = fmaf(vB, w.x, hB[4*j+0]);
                hB[4*j+1] = fmaf(vB, w.y, hB[4*j+1]);
                hB[4*j+2] = fmaf(vB, w.z, hB[4*j+2]);
                hB[4*j+3] = fmaf(vB, w.w, hB[4*j+3]);
            }
        }
        #pragma unroll
        for (int h = 0; h < 16; ++h) {
            const float vA = fmaxf(hA[h], 0.f);
            const float vB = fmaxf(hB[h], 0.f);
            #pragma unroll
            for (int j = 0; j < 4; ++j) {
                const float4 w = LDC4(cw.Wr2o, (base + h) * ED + 4 * j);
                roA[4*j+0] = fmaf(vA, w.x, roA[4*j+0]);
                roA[4*j+1] = fmaf(vA, w.y, roA[4*j+1]);
                roA[4*j+2] = fmaf(vA, w.z, roA[4*j+2]);
                roA[4*j+3] = fmaf(vA, w.w, roA[4*j+3]);
                roB[4*j+0] = fmaf(vB, w.x, roB[4*j+0]);
                roB[4*j+1] = fmaf(vB, w.y, roB[4*j+1]);
                roB[4*j+2] = fmaf(vB, w.z, roB[4*j+2]);
                roB[4*j+3] = fmaf(vB, w.w, roB[4*j+3]);
            }
        }
    }

    // ---- reload rn, dual psi head ----
    float rA[ED], rB[ED];
    #pragma unroll
    for (int i = 0; i < ED; ++i) { rA[i] = mySA[i]; rB[i] = mySB[i]; }

    const float4 gvA = xp[(size_t)20 * BMAX + t0];
    const float4 gvB = xp[(size_t)20 * BMAX + t1];
    const float gsA[4] = { gvA.x, gvA.y, gvA.z, gvA.w };
    const float gsB[4] = { gvB.x, gvB.y, gvB.z, gvB.w };
    float a0A = cw.bpsi2[0], a1A = cw.bpsi2[1];
    float a0B = a0A, a1B = a1A;

    #pragma unroll 1
    for (int c = 0; c < 4; ++c) {
        const int base = c * 16;
        float hA[16], hB[16];
        #pragma unroll
        for (int q = 0; q < 4; ++q) {
            const float4 b = LDC4(cw.bpsi1, base + 4 * q);
            hA[4*q+0] = b.x; hA[4*q+1] = b.y; hA[4*q+2] = b.z; hA[4*q+3] = b.w;
            hB[4*q+0] = b.x; hB[4*q+1] = b.y; hB[4*q+2] = b.z; hB[4*q+3] = b.w;
        }
        #pragma unroll
        for (int i = 0; i < ED; ++i) {
            const float vA = rA[i], vB = rB[i];
            #pragma unroll
            for (int j = 0; j < 4; ++j) {
                const float4 w = LDC4(cw.Wpsi1, i * HP + base + 4 * j);
                hA[4*j+0] = fmaf(vA, w.x, hA[4*j+0]);
                hA[4*j+1] = fmaf(vA, w.y, hA[4*j+1]);
                hA[4*j+2] = fmaf(vA, w.z, hA[4*j+2]);
                hA[4*j+3] = fmaf(vA, w.w, hA[4*j+3]);
                hB[4*j+0] = fmaf(vB, w.x, hB[4*j+0]);
                hB[4*j+1] = fmaf(vB, w.y, hB[4*j+1]);
                hB[4*j+2] = fmaf(vB, w.z, hB[4*j+2]);
                hB[4*j+3] = fmaf(vB, w.w, hB[4*j+3]);
            }
        }
        #pragma unroll
        for (int i = 0; i < ED; ++i) {
            const float vA = roA[i], vB = roB[i];
            #pragma unroll
            for (int j = 0; j < 4; ++j) {
                const float4 w = LDC4(cw.Wpsi1, (ED + i) * HP + base + 4 * j);
                hA[4*j+0] = fmaf(vA, w.x, hA[4*j+0]);
                hA[4*j+1] = fmaf(vA, w.y, hA[4*j+1]);
                hA[4*j+2] = fmaf(vA, w.z, hA[4*j+2]);
                hA[4*j+3] = fmaf(vA, w.w, hA[4*j+3]);
                hB[4*j+0] = fmaf(vB, w.x, hB[4*j+0]);
                hB[4*j+1] = fmaf(vB, w.y, hB[4*j+1]);
                hB[4*j+2] = fmaf(vB, w.z, hB[4*j+2]);
                hB[4*j+3] = fmaf(vB, w.w, hB[4*j+3]);
            }
        }
        #pragma unroll
        for (int k = 0; k < 4; ++k) {
            const float vA = gsA[k], vB = gsB[k];
            #pragma unroll
            for (int j = 0; j < 4; ++j) {
                const float4 w = LDC4(cw.Wpsi1, (2 * ED + k) * HP + base + 4 * j);
                hA[4*j+0] = fmaf(vA, w.x, hA[4*j+0]);
                hA[4*j+1] = fmaf(vA, w.y, hA[4*j+1]);
                hA[4*j+2] = fmaf(vA, w.z, hA[4*j+2]);
                hA[4*j+3] = fmaf(vA, w.w, hA[4*j+3]);
                hB[4*j+0] = fmaf(vB, w.x, hB[4*j+0]);
                hB[4*j+1] = fmaf(vB, w.y, hB[4*j+1]);
                hB[4*j+2] = fmaf(vB, w.z, hB[4*j+2]);
                hB[4*j+3] = fmaf(vB, w.w, hB[4*j+3]);
            }
        }
        #pragma unroll
        for (int h = 0; h < 16; h += 2) {
            const float4 w = LDC4(cw.Wpsi2, 2 * (base + h));
            const float uA0 = fmaxf(hA[h], 0.f),   uB0 = fmaxf(hB[h], 0.f);
            const float uA1 = fmaxf(hA[h+1], 0.f), uB1 = fmaxf(hB[h+1], 0.f);
            a0A = fmaf(uA0, w.x, a0A); a1A = fmaf(uA0, w.y, a1A);
            a0A = fmaf(uA1, w.z, a0A); a1A = fmaf(uA1, w.w, a1A);
            a0B = fmaf(uB0, w.x, a0B); a1B = fmaf(uB0, w.y, a1B);
            a0B = fmaf(uB1, w.z, a0B); a1B = fmaf(uB1, w.w, a1B);
        }
    }

    // ---- epilogues ----
    {
        float a0 = fmaf(2.0f, tanhf(a0A), bxA);
        float a1 = fmaf(2.0f, tanhf(a1A), byA);
        const float inv = fmaxf(fmaxf(fabsf(a0), fabsf(a1)) * 0.5f, 1.0f);
        const float r = __fdividef(1.0f, inv);
        float2 res; res.x = a0 * r; res.y = a1 * r;
        reinterpret_cast<float2*>(out)[t0] = res;
    }
    if (hasB) {
        float a0 = fmaf(2.0f, tanhf(a0B), bxB);
        float a1 = fmaf(2.0f, tanhf(a1B), byB);
        const float inv = fmaxf(fmaxf(fabsf(a0), fabsf(a1)) * 0.5f, 1.0f);
        const float r = __fdividef(1.0f, inv);
        float2 res; res.x = a0 * r; res.y = a1 * r;
        reinterpret_cast<float2*>(out)[t1] = res;
    }
}

extern "C" void kernel_launch(void* const* d_in, const int* in_sizes, int n_in,
                              void* d_out, int out_size) {
    const float* x = (const float*)d_in[0];
    float* out = (float*)d_out;
    const int nb = in_sizes[0] / XC;

    WPtrs w;
    for (int i = 0; i < 20; ++i) w.p[i] = (const float*)d_in[i + 1];

    const int nbBlocks = (nb + 31) / 32;
    prep_kernel<<<nbBlocks + 18, 256>>>(x, nb, nbBlocks, w);

    void* blobAddr = nullptr;
    cudaGetSymbolAddress(&blobAddr, g_wblob);
    cudaMemcpyToSymbolAsync(cw, blobAddr, sizeof(CW), 0, cudaMemcpyDeviceToDevice, 0);

    const int blocks = (nb + 2 * TPB - 1) / (2 * TPB);
    bnet_kernel<<<blocks, TPB>>>(out, nb);
}

// round 16
// speedup vs baseline: 1.6419x; 1.5025x over previous
#include <cuda_runtime.h>
#include <math.h>

#define NNB  16
#define NOB  8
#define SDIM 4
#define H1   64
#define ED   16
#define HP   64
#define XC   85
#define BMAX 131072
#define NGRP 21
#define TPB  256

__device__ float g_xP[XC * BMAX];

struct __align__(16) CW {
    float Wp1n_t[H1 * 4];
    float bp1n[H1];
    float Wp2n[H1 * ED];
    float bp2n[ED];         // pre-scaled by NNB
    float Wr1n[ED * H1];
    float br1n[H1];
    float Wr2n[H1 * ED];
    float br2n[ED];
    float Wp1o_t[H1 * 2];
    float bp1o[H1];
    float Wp2o[H1 * ED];
    float bp2o[ED];         // pre-scaled by NOB
    float Wr1o[ED * H1];
    float br1o[H1];
    float Wr2o[H1 * ED];
    float br2o[ED];
    float Wpsi1[(2 * ED + SDIM) * HP];
    float bpsi1[HP];
    float Wpsi2[HP * 2];
    float bpsi2[2];
    float pad[2];
};

__constant__ CW cw;
__device__ CW g_wblob;

struct WPtrs { const float* p[20]; };

#define LDC4(arr, off) (*reinterpret_cast<const float4*>(&(arr)[off]))
#define LDC2(arr, off) (*reinterpret_cast<const float2*>(&(arr)[off]))
#define LDS4(arr, off) (*reinterpret_cast<const float4*>(&(arr)[off]))

// ---------------- prep kernel (unchanged from R13) ----------------
__global__ void __launch_bounds__(256)
prep_kernel(const float* __restrict__ x, int nb, int nbBlocks, WPtrs w)
{
    if (blockIdx.x >= (unsigned)nbBlocks) {
        const int a = blockIdx.x - nbBlocks;
        const int tid = threadIdx.x;
        if (a == 16) {
            for (int i = tid; i < H1 * 4; i += 256) {
                int h = i >> 2, k = i & 3;
                g_wblob.Wp1n_t[i] = w.p[0][k * H1 + h];
            }
        } else if (a == 17) {
            for (int i = tid; i < H1 * 2; i += 256) {
                int h = i >> 1, k = i & 1;
                g_wblob.Wp1o_t[i] = w.p[8][k * H1 + h];
            }
            for (int i = tid; i < ED; i += 256) {
                g_wblob.bp2n[i] = (float)NNB * w.p[3][i];
                g_wblob.bp2o[i] = (float)NOB * w.p[11][i];
            }
        } else {
            float* dsts[16] = { g_wblob.bp1n, g_wblob.Wp2n, g_wblob.Wr1n, g_wblob.br1n,
                                g_wblob.Wr2n, g_wblob.br2n,
                                g_wblob.bp1o, g_wblob.Wp2o, g_wblob.Wr1o, g_wblob.br1o,
                                g_wblob.Wr2o, g_wblob.br2o,
                                g_wblob.Wpsi1, g_wblob.bpsi1, g_wblob.Wpsi2, g_wblob.bpsi2 };
            const int srci[16] = { 1, 2, 4, 5, 6, 7, 9, 10, 12, 13, 14, 15, 16, 17, 18, 19 };
            const int ns[16]   = { H1, H1*ED, ED*H1, H1, H1*ED, ED,
                                   H1, H1*ED, ED*H1, H1, H1*ED, ED,
                                   (2*ED+SDIM)*HP, HP, HP*2, 2 };
            float* dst = dsts[a];
            const float* src = w.p[srci[a]];
            const int n = ns[a];
            for (int i = tid; i < n; i += 256)
                dst[i] = src[i];
        }
        return;
    }

    __shared__ __align__(16) float buf[32 * 85];
    const int bBase = blockIdx.x * 32;

    if (bBase + 32 <= nb) {
        const float4* src = reinterpret_cast<const float4*>(x + (size_t)bBase * 85);
        float4* dst = reinterpret_cast<float4*>(buf);
        #pragma unroll 4
        for (int i = threadIdx.x; i < 680; i += 256)
            dst[i] = src[i];
    } else {
        for (int i = threadIdx.x; i < 32 * 85; i += 256) {
            const int r = i / 85, f = i - 85 * r;
            const int b = bBase + r;
            buf[i] = (b < nb) ? x[(size_t)b * 85 + f] : 0.f;
        }
    }
    __syncthreads();

    const int bl = threadIdx.x & 31;
    const int b  = bBase + bl;
    if (b < nb) {
        const float* row = buf + bl * 85;
        for (int g = threadIdx.x >> 5; g < NGRP; g += 8) {
            const int fb = (g < 16) ? (5 + 4 * g) : (g < 20 ? (69 + 4 * (g - 16)) : 1);
            float4 v;
            v.x = row[fb];     v.y = row[fb + 1];
            v.z = row[fb + 2]; v.w = row[fb + 3];
            *reinterpret_cast<float4*>(&g_xP[((size_t)g * BMAX + b) * 4]) = v;
        }
    }
}

__device__ __forceinline__ void barrier_acc(float e0, float e1, float D,
                                            float& bx, float& by) {
    const float px = -e0, py = -e1;
    const float q  = fmaf(px, px, py * py);
    const float rq = rsqrtf(q);
    const float nrm = q * rq;
    const float s  = 0.05f * __fdividef(1.0f, nrm * (nrm - D));
    bx = fmaf(s, px, bx);
    by = fmaf(s, py, by);
}

// ======================= main kernel (R13 structure; rho weights in SMEM) =======================
__global__ void __launch_bounds__(TPB, 2)
bnet_kernel(float* __restrict__ out, int nb)
{
    // rho-net GEMV weights in shared memory (split traffic off the const port)
    __shared__ __align__(16) float sWr1n[ED * H1];
    __shared__ __align__(16) float sWr2n[H1 * ED];
    __shared__ __align__(16) float sWr1o[ED * H1];
    __shared__ __align__(16) float sWr2o[H1 * ED];

    {
        const int tid = threadIdx.x;   // 256 threads, each array = 256 float4
        reinterpret_cast<float4*>(sWr1n)[tid] = reinterpret_cast<const float4*>(g_wblob.Wr1n)[tid];
        reinterpret_cast<float4*>(sWr2n)[tid] = reinterpret_cast<const float4*>(g_wblob.Wr2n)[tid];
        reinterpret_cast<float4*>(sWr1o)[tid] = reinterpret_cast<const float4*>(g_wblob.Wr1o)[tid];
        reinterpret_cast<float4*>(sWr2o)[tid] = reinterpret_cast<const float4*>(g_wblob.Wr2o)[tid];
    }
    __syncthreads();

    const int t = blockIdx.x * TPB + threadIdx.x;
    if (t >= nb) return;

    const float4* xp = reinterpret_cast<const float4*>(g_xP);

    float bx = 0.f, by = 0.f;
    float rn[ED], ro[ED], sp[ED];

    // ======================= neighbor deep-set =======================
    {
        float hs[H1];
        #pragma unroll
        for (int h = 0; h < H1; ++h) hs[h] = 0.f;

        #pragma unroll 1
        for (int g = 0; g < 2; ++g) {
            float e[32];
            #pragma unroll
            for (int j = 0; j < 8; ++j) {
                const float4 v = xp[(size_t)(8 * g + j) * BMAX + t];
                e[4*j+0] = v.x; e[4*j+1] = v.y; e[4*j+2] = v.z; e[4*j+3] = v.w;
            }
            #pragma unroll
            for (int k = 0; k < 8; ++k)
                barrier_acc(e[4*k+0], e[4*k+1], 0.3f, bx, by);

            #pragma unroll
            for (int h = 0; h < H1; ++h) {
                const float4 w = LDC4(cw.Wp1n_t, h * 4);
                const float b  = cw.bp1n[h];
                float v0 = b, v1 = b, v2 = b, v3 = b;
                float v4 = b, v5 = b, v6 = b, v7 = b;
                v0 = fmaf(e[0],  w.x, v0); v0 = fmaf(e[1],  w.y, v0);
                v0 = fmaf(e[2],  w.z, v0); v0 = fmaf(e[3],  w.w, v0);
                v1 = fmaf(e[4],  w.x, v1); v1 = fmaf(e[5],  w.y, v1);
                v1 = fmaf(e[6],  w.z, v1); v1 = fmaf(e[7],  w.w, v1);
                v2 = fmaf(e[8],  w.x, v2); v2 = fmaf(e[9],  w.y, v2);
                v2 = fmaf(e[10], w.z, v2); v2 = fmaf(e[11], w.w, v2);
                v3 = fmaf(e[12], w.x, v3); v3 = fmaf(e[13], w.y, v3);
                v3 = fmaf(e[14], w.z, v3); v3 = fmaf(e[15], w.w, v3);
                v4 = fmaf(e[16], w.x, v4); v4 = fmaf(e[17], w.y, v4);
                v4 = fmaf(e[18], w.z, v4); v4 = fmaf(e[19], w.w, v4);
                v5 = fmaf(e[20], w.x, v5); v5 = fmaf(e[21], w.y, v5);
                v5 = fmaf(e[22], w.z, v5); v5 = fmaf(e[23], w.w, v5);
                v6 = fmaf(e[24], w.x, v6); v6 = fmaf(e[25], w.y, v6);
                v6 = fmaf(e[26], w.z, v6); v6 = fmaf(e[27], w.w, v6);
                v7 = fmaf(e[28], w.x, v7); v7 = fmaf(e[29], w.y, v7);
                v7 = fmaf(e[30], w.z, v7); v7 = fmaf(e[31], w.w, v7);
                const float s0 = (fmaxf(v0, 0.f) + fmaxf(v1, 0.f))
                               + (fmaxf(v2, 0.f) + fmaxf(v3, 0.f));
                const float s1 = (fmaxf(v4, 0.f) + fmaxf(v5, 0.f))
                               + (fmaxf(v6, 0.f) + fmaxf(v7, 0.f));
                hs[h] += s0 + s1;
            }
        }

        #pragma unroll
        for (int j = 0; j < 4; ++j) {
            const float4 b = LDC4(cw.bp2n, 4 * j);
            sp[4*j+0] = b.x; sp[4*j+1] = b.y; sp[4*j+2] = b.z; sp[4*j+3] = b.w;
        }
        #pragma unroll
        for (int h = 0; h < H1; ++h) {
            const float v = hs[h];
            #pragma unroll
            for (int j = 0; j < 4; ++j) {
                const float4 w = LDC4(cw.Wp2n, h * ED + 4 * j);
                sp[4*j+0] = fmaf(v, w.x, sp[4*j+0]);
                sp[4*j+1] = fmaf(v, w.y, sp[4*j+1]);
                sp[4*j+2] = fmaf(v, w.z, sp[4*j+2]);
                sp[4*j+3] = fmaf(v, w.w, sp[4*j+3]);
            }
        }
    }
    // rho_n (weights from SMEM)
    #pragma unroll
    for (int j = 0; j < 4; ++j) {
        const float4 b = LDC4(cw.br2n, 4 * j);
        rn[4*j+0] = b.x; rn[4*j+1] = b.y; rn[4*j+2] = b.z; rn[4*j+3] = b.w;
    }
    #pragma unroll 1
    for (int c = 0; c < 4; ++c) {
        const int base = c * 16;
        float hc[16];
        #pragma unroll
        for (int q = 0; q < 4; ++q) {
            const float4 b = LDC4(cw.br1n, base + 4 * q);
            hc[4*q+0] = b.x; hc[4*q+1] = b.y; hc[4*q+2] = b.z; hc[4*q+3] = b.w;
        }
        #pragma unroll
        for (int i = 0; i < ED; ++i) {
            const float v = sp[i];
            #pragma unroll
            for (int j = 0; j < 4; ++j) {
                const float4 w = LDS4(sWr1n, i * H1 + base + 4 * j);
                hc[4*j+0] = fmaf(v, w.x, hc[4*j+0]);
                hc[4*j+1] = fmaf(v, w.y, hc[4*j+1]);
                hc[4*j+2] = fmaf(v, w.z, hc[4*j+2]);
                hc[4*j+3] = fmaf(v, w.w, hc[4*j+3]);
            }
        }
        #pragma unroll
        for (int h = 0; h < 16; ++h) {
            const float v = fmaxf(hc[h], 0.f);
            #pragma unroll
            for (int j = 0; j < 4; ++j) {
                const float4 w = LDS4(sWr2n, (base + h) * ED + 4 * j);
                rn[4*j+0] = fmaf(v, w.x, rn[4*j+0]);
                rn[4*j+1] = fmaf(v, w.y, rn[4*j+1]);
                rn[4*j+2] = fmaf(v, w.z, rn[4*j+2]);
                rn[4*j+3] = fmaf(v, w.w, rn[4*j+3]);
            }
        }
    }

    // ======================= obstacle deep-set =======================
    {
        float e[16];
        #pragma unroll
        for (int j = 0; j < 4; ++j) {
            const float4 v = xp[(size_t)(16 + j) * BMAX + t];
            e[4*j+0] = v.x; e[4*j+1] = v.y; e[4*j+2] = v.z; e[4*j+3] = v.w;
        }
        #pragma unroll
        for (int k = 0; k < 8; ++k)
            barrier_acc(e[2*k+0], e[2*k+1], 0.3f, bx, by);

        float hs[H1];
        #pragma unroll
        for (int h = 0; h < H1; ++h) {
            const float2 w = LDC2(cw.Wp1o_t, h * 2);
            const float b  = cw.bp1o[h];
            float acc0 = 0.f, acc1 = 0.f;
            #pragma unroll
            for (int k = 0; k < 8; k += 2) {
                float va = b, vb = b;
                va = fmaf(e[2*k+0], w.x, va);
                va = fmaf(e[2*k+1], w.y, va);
                vb = fmaf(e[2*k+2], w.x, vb);
                vb = fmaf(e[2*k+3], w.y, vb);
                acc0 += fmaxf(va, 0.f);
                acc1 += fmaxf(vb, 0.f);
            }
            hs[h] = acc0 + acc1;
        }

        #pragma unroll
        for (int j = 0; j < 4; ++j) {
            const float4 b = LDC4(cw.bp2o, 4 * j);
            sp[4*j+0] = b.x; sp[4*j+1] = b.y; sp[4*j+2] = b.z; sp[4*j+3] = b.w;
        }
        #pragma unroll
        for (int h = 0; h < H1; ++h) {
            const float v = hs[h];
            #pragma unroll
            for (int j = 0; j < 4; ++j) {
                const float4 w = LDC4(cw.Wp2o, h * ED + 4 * j);
                sp[4*j+0] = fmaf(v, w.x, sp[4*j+0]);
                sp[4*j+1] = fmaf(v, w.y, sp[4*j+1]);
                sp[4*j+2] = fmaf(v, w.z, sp[4*j+2]);
                sp[4*j+3] = fmaf(v, w.w, sp[4*j+3]);
            }
        }
    }
    // rho_o (weights from SMEM)
    #pragma unroll
    for (int j = 0; j < 4; ++j) {
        const float4 b = LDC4(cw.br2o, 4 * j);
        ro[4*j+0] = b.x; ro[4*j+1] = b.y; ro[4*j+2] = b.z; ro[4*j+3] = b.w;
    }
    #pragma unroll 1
    for (int c = 0; c < 4; ++c) {
        const int base = c * 16;
        float hc[16];
        #pragma unroll
        for (int q = 0; q < 4; ++q) {
            const float4 b = LDC4(cw.br1o, base + 4 * q);
            hc[4*q+0] = b.x; hc[4*q+1] = b.y; hc[4*q+2] = b.z; hc[4*q+3] = b.w;
        }
        #pragma unroll
        for (int i = 0; i < ED; ++i) {
            const float v = sp[i];
            #pragma unroll
            for (int j = 0; j < 4; ++j) {
                const float4 w = LDS4(sWr1o, i * H1 + base + 4 * j);
                hc[4*j+0] = fmaf(v, w.x, hc[4*j+0]);
                hc[4*j+1] = fmaf(v, w.y, hc[4*j+1]);
                hc[4*j+2] = fmaf(v, w.z, hc[4*j+2]);
                hc[4*j+3] = fmaf(v, w.w, hc[4*j+3]);
            }
        }
        #pragma unroll
        for (int h = 0; h < 16; ++h) {
            const float v = fmaxf(hc[h], 0.f);
            #pragma unroll
            for (int j = 0; j < 4; ++j) {
                const float4 w = LDS4(sWr2o, (base + h) * ED + 4 * j);
                ro[4*j+0] = fmaf(v, w.x, ro[4*j+0]);
                ro[4*j+1] = fmaf(v, w.y, ro[4*j+1]);
                ro[4*j+2] = fmaf(v, w.z, ro[4*j+2]);
                ro[4*j+3] = fmaf(v, w.w, ro[4*j+3]);
            }
        }
    }

    // ======================= psi head (const) =======================
    const float4 gv = xp[(size_t)20 * BMAX + t];
    const float gs[4] = { gv.x, gv.y, gv.z, gv.w };
    float a0 = cw.bpsi2[0], a1 = cw.bpsi2[1];
    #pragma unroll 1
    for (int c = 0; c < 4; ++c) {
        const int base = c * 16;
        float hc[16];
        #pragma unroll
        for (int q = 0; q < 4; ++q) {
            const float4 b = LDC4(cw.bpsi1, base + 4 * q);
            hc[4*q+0] = b.x; hc[4*q+1] = b.y; hc[4*q+2] = b.z; hc[4*q+3] = b.w;
        }
        #pragma unroll
        for (int i = 0; i < ED; ++i) {
            const float v = rn[i];
            #pragma unroll
            for (int j = 0; j < 4; ++j) {
                const float4 w = LDC4(cw.Wpsi1, i * HP + base + 4 * j);
                hc[4*j+0] = fmaf(v, w.x, hc[4*j+0]);
                hc[4*j+1] = fmaf(v, w.y, hc[4*j+1]);
                hc[4*j+2] = fmaf(v, w.z, hc[4*j+2]);
                hc[4*j+3] = fmaf(v, w.w, hc[4*j+3]);
            }
        }
        #pragma unroll
        for (int i = 0; i < ED; ++i) {
            const float v = ro[i];
            #pragma unroll
            for (int j = 0; j < 4; ++j) {
                const float4 w = LDC4(cw.Wpsi1, (ED + i) * HP + base + 4 * j);
                hc[4*j+0] = fmaf(v, w.x, hc[4*j+0]);
                hc[4*j+1] = fmaf(v, w.y, hc[4*j+1]);
                hc[4*j+2] = fmaf(v, w.z, hc[4*j+2]);
                hc[4*j+3] = fmaf(v, w.w, hc[4*j+3]);
            }
        }
        #pragma unroll
        for (int k = 0; k < 4; ++k) {
            const float v = gs[k];
            #pragma unroll
            for (int j = 0; j < 4; ++j) {
                const float4 w = LDC4(cw.Wpsi1, (2 * ED + k) * HP + base + 4 * j);
                hc[4*j+0] = fmaf(v, w.x, hc[4*j+0]);
                hc[4*j+1] = fmaf(v, w.y, hc[4*j+1]);
                hc[4*j+2] = fmaf(v, w.z, hc[4*j+2]);
                hc[4*j+3] = fmaf(v, w.w, hc[4*j+3]);
            }
        }
        #pragma unroll
        for (int h = 0; h < 16; h += 2) {
            const float v0 = fmaxf(hc[h], 0.f);
            const float v1 = fmaxf(hc[h + 1], 0.f);
            const float4 w = LDC4(cw.Wpsi2, 2 * (base + h));
            a0 = fmaf(v0, w.x, a0); a1 = fmaf(v0, w.y, a1);
            a0 = fmaf(v1, w.z, a0); a1 = fmaf(v1, w.w, a1);
        }
    }

    a0 = fmaf(2.0f, tanhf(a0), bx);
    a1 = fmaf(2.0f, tanhf(a1), by);

    const float inv = fmaxf(fmaxf(fabsf(a0), fabsf(a1)) * 0.5f, 1.0f);
    const float r   = __fdividef(1.0f, inv);
    float2 res;
    res.x = a0 * r;
    res.y = a1 * r;
    reinterpret_cast<float2*>(out)[t] = res;
}

extern "C" void kernel_launch(void* const* d_in, const int* in_sizes, int n_in,
                              void* d_out, int out_size) {
    const float* x = (const float*)d_in[0];
    float* out = (float*)d_out;
    const int nb = in_sizes[0] / XC;

    WPtrs w;
    for (int i = 0; i < 20; ++i) w.p[i] = (const float*)d_in[i + 1];

    const int nbBlocks = (nb + 31) / 32;
    prep_kernel<<<nbBlocks + 18, 256>>>(x, nb, nbBlocks, w);

    void* blobAddr = nullptr;
    cudaGetSymbolAddress(&blobAddr, g_wblob);
    cudaMemcpyToSymbolAsync(cw, blobAddr, sizeof(CW), 0, cudaMemcpyDeviceToDevice, 0);

    const int blocks = (nb + TPB - 1) / TPB;
    bnet_kernel<<<blocks, TPB>>>(out, nb);
}

// round 17
// speedup vs baseline: 1.6464x; 1.0028x over previous
#include <cuda_runtime.h>
#include <math.h>

#define NNB  16
#define NOB  8
#define SDIM 4
#define H1   64
#define ED   16
#define HP   64
#define XC   85
#define BMAX 131072
#define NGRP 21
#define TPB  256

__device__ float g_xP[XC * BMAX];

struct __align__(16) CW {
    float Wp1n_t[H1 * 4];
    float bp1n[H1];
    float Wp2n[H1 * ED];
    float bp2n[ED];         // pre-scaled by NNB
    float Wr1n[ED * H1];
    float br1n[H1];
    float Wr2n[H1 * ED];
    float br2n[ED];
    float Wp1o_t[H1 * 2];
    float bp1o[H1];
    float Wp2o[H1 * ED];
    float bp2o[ED];         // pre-scaled by NOB
    float Wr1o[ED * H1];
    float br1o[H1];
    float Wr2o[H1 * ED];
    float br2o[ED];
    float Wpsi1[(2 * ED + SDIM) * HP];
    float bpsi1[HP];
    float Wpsi2[HP * 2];
    float bpsi2[2];
    float pad[2];
};

__constant__ CW cw;
__device__ CW g_wblob;

struct WPtrs { const float* p[20]; };

#define LDC4(arr, off) (*reinterpret_cast<const float4*>(&(arr)[off]))
#define LDC2(arr, off) (*reinterpret_cast<const float2*>(&(arr)[off]))
#define LDS4(arr, off) (*reinterpret_cast<const float4*>(&(arr)[off]))

// ---------------- prep kernel (unchanged) ----------------
__global__ void __launch_bounds__(256)
prep_kernel(const float* __restrict__ x, int nb, int nbBlocks, WPtrs w)
{
    if (blockIdx.x >= (unsigned)nbBlocks) {
        const int a = blockIdx.x - nbBlocks;
        const int tid = threadIdx.x;
        if (a == 16) {
            for (int i = tid; i < H1 * 4; i += 256) {
                int h = i >> 2, k = i & 3;
                g_wblob.Wp1n_t[i] = w.p[0][k * H1 + h];
            }
        } else if (a == 17) {
            for (int i = tid; i < H1 * 2; i += 256) {
                int h = i >> 1, k = i & 1;
                g_wblob.Wp1o_t[i] = w.p[8][k * H1 + h];
            }
            for (int i = tid; i < ED; i += 256) {
                g_wblob.bp2n[i] = (float)NNB * w.p[3][i];
                g_wblob.bp2o[i] = (float)NOB * w.p[11][i];
            }
        } else {
            float* dsts[16] = { g_wblob.bp1n, g_wblob.Wp2n, g_wblob.Wr1n, g_wblob.br1n,
                                g_wblob.Wr2n, g_wblob.br2n,
                                g_wblob.bp1o, g_wblob.Wp2o, g_wblob.Wr1o, g_wblob.br1o,
                                g_wblob.Wr2o, g_wblob.br2o,
                                g_wblob.Wpsi1, g_wblob.bpsi1, g_wblob.Wpsi2, g_wblob.bpsi2 };
            const int srci[16] = { 1, 2, 4, 5, 6, 7, 9, 10, 12, 13, 14, 15, 16, 17, 18, 19 };
            const int ns[16]   = { H1, H1*ED, ED*H1, H1, H1*ED, ED,
                                   H1, H1*ED, ED*H1, H1, H1*ED, ED,
                                   (2*ED+SDIM)*HP, HP, HP*2, 2 };
            float* dst = dsts[a];
            const float* src = w.p[srci[a]];
            const int n = ns[a];
            for (int i = tid; i < n; i += 256)
                dst[i] = src[i];
        }
        return;
    }

    __shared__ __align__(16) float buf[32 * 85];
    const int bBase = blockIdx.x * 32;

    if (bBase + 32 <= nb) {
        const float4* src = reinterpret_cast<const float4*>(x + (size_t)bBase * 85);
        float4* dst = reinterpret_cast<float4*>(buf);
        #pragma unroll 4
        for (int i = threadIdx.x; i < 680; i += 256)
            dst[i] = src[i];
    } else {
        for (int i = threadIdx.x; i < 32 * 85; i += 256) {
            const int r = i / 85, f = i - 85 * r;
            const int b = bBase + r;
            buf[i] = (b < nb) ? x[(size_t)b * 85 + f] : 0.f;
        }
    }
    __syncthreads();

    const int bl = threadIdx.x & 31;
    const int b  = bBase + bl;
    if (b < nb) {
        const float* row = buf + bl * 85;
        for (int g = threadIdx.x >> 5; g < NGRP; g += 8) {
            const int fb = (g < 16) ? (5 + 4 * g) : (g < 20 ? (69 + 4 * (g - 16)) : 1);
            float4 v;
            v.x = row[fb];     v.y = row[fb + 1];
            v.z = row[fb + 2]; v.w = row[fb + 3];
            *reinterpret_cast<float4*>(&g_xP[((size_t)g * BMAX + b) * 4]) = v;
        }
    }
}

__device__ __forceinline__ void barrier_acc(float e0, float e1, float D,
                                            float& bx, float& by) {
    const float px = -e0, py = -e1;
    const float q  = fmaf(px, px, py * py);
    const float rq = rsqrtf(q);
    const float nrm = q * rq;
    const float s  = 0.05f * __fdividef(1.0f, nrm * (nrm - D));
    bx = fmaf(s, px, bx);
    by = fmaf(s, py, by);
}

// ======================= main kernel (rho + Wp2 weights in SMEM) =======================
__global__ void __launch_bounds__(TPB, 2)
bnet_kernel(float* __restrict__ out, int nb)
{
    __shared__ __align__(16) float sWr1n[ED * H1];
    __shared__ __align__(16) float sWr2n[H1 * ED];
    __shared__ __align__(16) float sWr1o[ED * H1];
    __shared__ __align__(16) float sWr2o[H1 * ED];
    __shared__ __align__(16) float sWp2n[H1 * ED];
    __shared__ __align__(16) float sWp2o[H1 * ED];

    {
        const int tid = threadIdx.x;   // 256 threads; each array = 256 float4
        reinterpret_cast<float4*>(sWr1n)[tid] = reinterpret_cast<const float4*>(g_wblob.Wr1n)[tid];
        reinterpret_cast<float4*>(sWr2n)[tid] = reinterpret_cast<const float4*>(g_wblob.Wr2n)[tid];
        reinterpret_cast<float4*>(sWr1o)[tid] = reinterpret_cast<const float4*>(g_wblob.Wr1o)[tid];
        reinterpret_cast<float4*>(sWr2o)[tid] = reinterpret_cast<const float4*>(g_wblob.Wr2o)[tid];
        reinterpret_cast<float4*>(sWp2n)[tid] = reinterpret_cast<const float4*>(g_wblob.Wp2n)[tid];
        reinterpret_cast<float4*>(sWp2o)[tid] = reinterpret_cast<const float4*>(g_wblob.Wp2o)[tid];
    }
    __syncthreads();

    const int t = blockIdx.x * TPB + threadIdx.x;
    if (t >= nb) return;

    const float4* xp = reinterpret_cast<const float4*>(g_xP);

    float bx = 0.f, by = 0.f;
    float rn[ED], ro[ED], sp[ED];

    // ======================= neighbor deep-set =======================
    {
        float hs[H1];
        #pragma unroll
        for (int h = 0; h < H1; ++h) hs[h] = 0.f;

        #pragma unroll 1
        for (int g = 0; g < 2; ++g) {
            float e[32];
            #pragma unroll
            for (int j = 0; j < 8; ++j) {
                const float4 v = xp[(size_t)(8 * g + j) * BMAX + t];
                e[4*j+0] = v.x; e[4*j+1] = v.y; e[4*j+2] = v.z; e[4*j+3] = v.w;
            }
            #pragma unroll
            for (int k = 0; k < 8; ++k)
                barrier_acc(e[4*k+0], e[4*k+1], 0.3f, bx, by);

            #pragma unroll
            for (int h = 0; h < H1; ++h) {
                const float4 w = LDC4(cw.Wp1n_t, h * 4);
                const float b  = cw.bp1n[h];
                float v0 = b, v1 = b, v2 = b, v3 = b;
                float v4 = b, v5 = b, v6 = b, v7 = b;
                v0 = fmaf(e[0],  w.x, v0); v0 = fmaf(e[1],  w.y, v0);
                v0 = fmaf(e[2],  w.z, v0); v0 = fmaf(e[3],  w.w, v0);
                v1 = fmaf(e[4],  w.x, v1); v1 = fmaf(e[5],  w.y, v1);
                v1 = fmaf(e[6],  w.z, v1); v1 = fmaf(e[7],  w.w, v1);
                v2 = fmaf(e[8],  w.x, v2); v2 = fmaf(e[9],  w.y, v2);
                v2 = fmaf(e[10], w.z, v2); v2 = fmaf(e[11], w.w, v2);
                v3 = fmaf(e[12], w.x, v3); v3 = fmaf(e[13], w.y, v3);
                v3 = fmaf(e[14], w.z, v3); v3 = fmaf(e[15], w.w, v3);
                v4 = fmaf(e[16], w.x, v4); v4 = fmaf(e[17], w.y, v4);
                v4 = fmaf(e[18], w.z, v4); v4 = fmaf(e[19], w.w, v4);
                v5 = fmaf(e[20], w.x, v5); v5 = fmaf(e[21], w.y, v5);
                v5 = fmaf(e[22], w.z, v5); v5 = fmaf(e[23], w.w, v5);
                v6 = fmaf(e[24], w.x, v6); v6 = fmaf(e[25], w.y, v6);
                v6 = fmaf(e[26], w.z, v6); v6 = fmaf(e[27], w.w, v6);
                v7 = fmaf(e[28], w.x, v7); v7 = fmaf(e[29], w.y, v7);
                v7 = fmaf(e[30], w.z, v7); v7 = fmaf(e[31], w.w, v7);
                const float s0 = (fmaxf(v0, 0.f) + fmaxf(v1, 0.f))
                               + (fmaxf(v2, 0.f) + fmaxf(v3, 0.f));
                const float s1 = (fmaxf(v4, 0.f) + fmaxf(v5, 0.f))
                               + (fmaxf(v6, 0.f) + fmaxf(v7, 0.f));
                hs[h] += s0 + s1;
            }
        }

        #pragma unroll
        for (int j = 0; j < 4; ++j) {
            const float4 b = LDC4(cw.bp2n, 4 * j);
            sp[4*j+0] = b.x; sp[4*j+1] = b.y; sp[4*j+2] = b.z; sp[4*j+3] = b.w;
        }
        #pragma unroll
        for (int h = 0; h < H1; ++h) {
            const float v = hs[h];
            #pragma unroll
            for (int j = 0; j < 4; ++j) {
                const float4 w = LDS4(sWp2n, h * ED + 4 * j);
                sp[4*j+0] = fmaf(v, w.x, sp[4*j+0]);
                sp[4*j+1] = fmaf(v, w.y, sp[4*j+1]);
                sp[4*j+2] = fmaf(v, w.z, sp[4*j+2]);
                sp[4*j+3] = fmaf(v, w.w, sp[4*j+3]);
            }
        }
    }
    // rho_n (SMEM weights)
    #pragma unroll
    for (int j = 0; j < 4; ++j) {
        const float4 b = LDC4(cw.br2n, 4 * j);
        rn[4*j+0] = b.x; rn[4*j+1] = b.y; rn[4*j+2] = b.z; rn[4*j+3] = b.w;
    }
    #pragma unroll 1
    for (int c = 0; c < 4; ++c) {
        const int base = c * 16;
        float hc[16];
        #pragma unroll
        for (int q = 0; q < 4; ++q) {
            const float4 b = LDC4(cw.br1n, base + 4 * q);
            hc[4*q+0] = b.x; hc[4*q+1] = b.y; hc[4*q+2] = b.z; hc[4*q+3] = b.w;
        }
        #pragma unroll
        for (int i = 0; i < ED; ++i) {
            const float v = sp[i];
            #pragma unroll
            for (int j = 0; j < 4; ++j) {
                const float4 w = LDS4(sWr1n, i * H1 + base + 4 * j);
                hc[4*j+0] = fmaf(v, w.x, hc[4*j+0]);
                hc[4*j+1] = fmaf(v, w.y, hc[4*j+1]);
                hc[4*j+2] = fmaf(v, w.z, hc[4*j+2]);
                hc[4*j+3] = fmaf(v, w.w, hc[4*j+3]);
            }
        }
        #pragma unroll
        for (int h = 0; h < 16; ++h) {
            const float v = fmaxf(hc[h], 0.f);
            #pragma unroll
            for (int j = 0; j < 4; ++j) {
                const float4 w = LDS4(sWr2n, (base + h) * ED + 4 * j);
                rn[4*j+0] = fmaf(v, w.x, rn[4*j+0]);
                rn[4*j+1] = fmaf(v, w.y, rn[4*j+1]);
                rn[4*j+2] = fmaf(v, w.z, rn[4*j+2]);
                rn[4*j+3] = fmaf(v, w.w, rn[4*j+3]);
            }
        }
    }

    // ======================= obstacle deep-set =======================
    {
        float e[16];
        #pragma unroll
        for (int j = 0; j < 4; ++j) {
            const float4 v = xp[(size_t)(16 + j) * BMAX + t];
            e[4*j+0] = v.x; e[4*j+1] = v.y; e[4*j+2] = v.z; e[4*j+3] = v.w;
        }
        #pragma unroll
        for (int k = 0; k < 8; ++k)
            barrier_acc(e[2*k+0], e[2*k+1], 0.3f, bx, by);

        float hs[H1];
        #pragma unroll
        for (int h = 0; h < H1; ++h) {
            const float2 w = LDC2(cw.Wp1o_t, h * 2);
            const float b  = cw.bp1o[h];
            float acc0 = 0.f, acc1 = 0.f;
            #pragma unroll
            for (int k = 0; k < 8; k += 2) {
                float va = b, vb = b;
                va = fmaf(e[2*k+0], w.x, va);
                va = fmaf(e[2*k+1], w.y, va);
                vb = fmaf(e[2*k+2], w.x, vb);
                vb = fmaf(e[2*k+3], w.y, vb);
                acc0 += fmaxf(va, 0.f);
                acc1 += fmaxf(vb, 0.f);
            }
            hs[h] = acc0 + acc1;
        }

        #pragma unroll
        for (int j = 0; j < 4; ++j) {
            const float4 b = LDC4(cw.bp2o, 4 * j);
            sp[4*j+0] = b.x; sp[4*j+1] = b.y; sp[4*j+2] = b.z; sp[4*j+3] = b.w;
        }
        #pragma unroll
        for (int h = 0; h < H1; ++h) {
            const float v = hs[h];
            #pragma unroll
            for (int j = 0; j < 4; ++j) {
                const float4 w = LDS4(sWp2o, h * ED + 4 * j);
                sp[4*j+0] = fmaf(v, w.x, sp[4*j+0]);
                sp[4*j+1] = fmaf(v, w.y, sp[4*j+1]);
                sp[4*j+2] = fmaf(v, w.z, sp[4*j+2]);
                sp[4*j+3] = fmaf(v, w.w, sp[4*j+3]);
            }
        }
    }
    // rho_o (SMEM weights)
    #pragma unroll
    for (int j = 0; j < 4; ++j) {
        const float4 b = LDC4(cw.br2o, 4 * j);
        ro[4*j+0] = b.x; ro[4*j+1] = b.y; ro[4*j+2] = b.z; ro[4*j+3] = b.w;
    }
    #pragma unroll 1
    for (int c = 0; c < 4; ++c) {
        const int base = c * 16;
        float hc[16];
        #pragma unroll
        for (int q = 0; q < 4; ++q) {
            const float4 b = LDC4(cw.br1o, base + 4 * q);
            hc[4*q+0] = b.x; hc[4*q+1] = b.y; hc[4*q+2] = b.z; hc[4*q+3] = b.w;
        }
        #pragma unroll
        for (int i = 0; i < ED; ++i) {
            const float v = sp[i];
            #pragma unroll
            for (int j = 0; j < 4; ++j) {
                const float4 w = LDS4(sWr1o, i * H1 + base + 4 * j);
                hc[4*j+0] = fmaf(v, w.x, hc[4*j+0]);
                hc[4*j+1] = fmaf(v, w.y, hc[4*j+1]);
                hc[4*j+2] = fmaf(v, w.z, hc[4*j+2]);
                hc[4*j+3] = fmaf(v, w.w, hc[4*j+3]);
            }
        }
        #pragma unroll
        for (int h = 0; h < 16; ++h) {
            const float v = fmaxf(hc[h], 0.f);
            #pragma unroll
            for (int j = 0; j < 4; ++j) {
                const float4 w = LDS4(sWr2o, (base + h) * ED + 4 * j);
                ro[4*j+0] = fmaf(v, w.x, ro[4*j+0]);
                ro[4*j+1] = fmaf(v, w.y, ro[4*j+1]);
                ro[4*j+2] = fmaf(v, w.z, ro[4*j+2]);
                ro[4*j+3] = fmaf(v, w.w, ro[4*j+3]);
            }
        }
    }

    // ======================= psi head (const) =======================
    const float4 gv = xp[(size_t)20 * BMAX + t];
    const float gs[4] = { gv.x, gv.y, gv.z, gv.w };
    float a0 = cw.bpsi2[0], a1 = cw.bpsi2[1];
    #pragma unroll 1
    for (int c = 0; c < 4; ++c) {
        const int base = c * 16;
        float hc[16];
        #pragma unroll
        for (int q = 0; q < 4; ++q) {
            const float4 b = LDC4(cw.bpsi1, base + 4 * q);
            hc[4*q+0] = b.x; hc[4*q+1] = b.y; hc[4*q+2] = b.z; hc[4*q+3] = b.w;
        }
        #pragma unroll
        for (int i = 0; i < ED; ++i) {
            const float v = rn[i];
            #pragma unroll
            for (int j = 0; j < 4; ++j) {
                const float4 w = LDC4(cw.Wpsi1, i * HP + base + 4 * j);
                hc[4*j+0] = fmaf(v, w.x, hc[4*j+0]);
                hc[4*j+1] = fmaf(v, w.y, hc[4*j+1]);
                hc[4*j+2] = fmaf(v, w.z, hc[4*j+2]);
                hc[4*j+3] = fmaf(v, w.w, hc[4*j+3]);
            }
        }
        #pragma unroll
        for (int i = 0; i < ED; ++i) {
            const float v = ro[i];
            #pragma unroll
            for (int j = 0; j < 4; ++j) {
                const float4 w = LDC4(cw.Wpsi1, (ED + i) * HP + base + 4 * j);
                hc[4*j+0] = fmaf(v, w.x, hc[4*j+0]);
                hc[4*j+1] = fmaf(v, w.y, hc[4*j+1]);
                hc[4*j+2] = fmaf(v, w.z, hc[4*j+2]);
                hc[4*j+3] = fmaf(v, w.w, hc[4*j+3]);
            }
        }
        #pragma unroll
        for (int k = 0; k < 4; ++k) {
            const float v = gs[k];
            #pragma unroll
            for (int j = 0; j < 4; ++j) {
                const float4 w = LDC4(cw.Wpsi1, (2 * ED + k) * HP + base + 4 * j);
                hc[4*j+0] = fmaf(v, w.x, hc[4*j+0]);
                hc[4*j+1] = fmaf(v, w.y, hc[4*j+1]);
                hc[4*j+2] = fmaf(v, w.z, hc[4*j+2]);
                hc[4*j+3] = fmaf(v, w.w, hc[4*j+3]);
            }
        }
        #pragma unroll
        for (int h = 0; h < 16; h += 2) {
            const float v0 = fmaxf(hc[h], 0.f);
            const float v1 = fmaxf(hc[h + 1], 0.f);
            const float4 w = LDC4(cw.Wpsi2, 2 * (base + h));
            a0 = fmaf(v0, w.x, a0); a1 = fmaf(v0, w.y, a1);
            a0 = fmaf(v1, w.z, a0); a1 = fmaf(v1, w.w, a1);
        }
    }

    a0 = fmaf(2.0f, tanhf(a0), bx);
    a1 = fmaf(2.0f, tanhf(a1), by);

    const float inv = fmaxf(fmaxf(fabsf(a0), fabsf(a1)) * 0.5f, 1.0f);
    const float r   = __fdividef(1.0f, inv);
    float2 res;
    res.x = a0 * r;
    res.y = a1 * r;
    reinterpret_cast<float2*>(out)[t] = res;
}

extern "C" void kernel_launch(void* const* d_in, const int* in_sizes, int n_in,
                              void* d_out, int out_size) {
    const float* x = (const float*)d_in[0];
    float* out = (float*)d_out;
    const int nb = in_sizes[0] / XC;

    WPtrs w;
    for (int i = 0; i < 20; ++i) w.p[i] = (const float*)d_in[i + 1];

    const int nbBlocks = (nb + 31) / 32;
    prep_kernel<<<nbBlocks + 18, 256>>>(x, nb, nbBlocks, w);

    void* blobAddr = nullptr;
    cudaGetSymbolAddress(&blobAddr, g_wblob);
    cudaMemcpyToSymbolAsync(cw, blobAddr, sizeof(CW), 0, cudaMemcpyDeviceToDevice, 0);

    const int blocks = (nb + TPB - 1) / TPB;
    bnet_kernel<<<blocks, TPB>>>(out, nb);
}